// round 11
// baseline (speedup 1.0000x reference)
#include <cuda_runtime.h>
#include <cuda_fp16.h>
#include <cstdint>
#include <cstddef>

#define DINLINE __device__ __forceinline__

static constexpr int BATCH = 4096;
static constexpr int ROWS  = BATCH * 2;   // 8192 GEMM rows (b*2+p)
static constexpr int FEAT  = 41024;       // K
static constexpr int MOUT  = 512;         // N

// GEMM tiling: CTA 256x128, 256 threads, warp grid 4(M) x 2(N), warp tile 64x64
static constexpr int TILE_M = 256;
static constexpr int TILE_N = 128;
static constexpr int KC     = 64;               // fp16 K per stage (128B rows)
static constexpr int NSTAGE = FEAT / KC;        // 641 exact

static constexpr unsigned OFF_A  = 0u;          // A tile  256x64 fp16 = 32KB
static constexpr unsigned OFF_BH = 32768u;      // Bhi 128x64 fp16 = 16KB
static constexpr unsigned OFF_BL = 49152u;      // Blo 16KB
static constexpr unsigned BUF_STRIDE = 65536u;  // 64KB per stage
static constexpr unsigned DYN_SMEM = 1024u + 2u * BUF_STRIDE;  // 132 KB

static constexpr size_t NFEL = (size_t)ROWS * FEAT;
static constexpr size_t NWEL = (size_t)MOUT * FEAT;
static constexpr size_t NF4  = NFEL / 4;
static constexpr size_t NW4  = NWEL / 4;

__device__ __align__(256) __half g_feat_h[NFEL];   // 672 MB
__device__ __align__(256) __half g_w_hi[NWEL];     // 42 MB
__device__ __align__(256) __half g_w_lo[NWEL];     // 42 MB
__device__ __align__(256) float  g_acc[(size_t)ROWS * MOUT];  // 16 MB

// ---------------- PTX helpers (base ISA only: sm_80+) ----------------
DINLINE uint32_t smem_u32(const void* p) {
    uint32_t a;
    asm("{ .reg .u64 t; cvta.to.shared.u64 t, %1; cvt.u32.u64 %0, t; }" : "=r"(a) : "l"(p));
    return a;
}
DINLINE void cp_async16(uint32_t dst, const void* src) {
    asm volatile("cp.async.cg.shared.global [%0], [%1], 16;" :: "r"(dst), "l"(src) : "memory");
}
DINLINE void cp_commit() { asm volatile("cp.async.commit_group;" ::: "memory"); }
template <int N> DINLINE void cp_wait() { asm volatile("cp.async.wait_group %0;" :: "n"(N) : "memory"); }

DINLINE void ldsm_x4(uint32_t& r0, uint32_t& r1, uint32_t& r2, uint32_t& r3, uint32_t a) {
    asm volatile("ldmatrix.sync.aligned.m8n8.x4.shared.b16 {%0,%1,%2,%3}, [%4];"
                 : "=r"(r0), "=r"(r1), "=r"(r2), "=r"(r3) : "r"(a));
}
DINLINE void mma16816(float* c, const uint32_t* a, const uint32_t* b) {
    asm volatile(
        "mma.sync.aligned.m16n8k16.row.col.f32.f16.f16.f32 "
        "{%0,%1,%2,%3}, {%4,%5,%6,%7}, {%8,%9}, {%0,%1,%2,%3};"
        : "+f"(c[0]), "+f"(c[1]), "+f"(c[2]), "+f"(c[3])
        : "r"(a[0]), "r"(a[1]), "r"(a[2]), "r"(a[3]), "r"(b[0]), "r"(b[1]));
}

// ---------------- kernel 1a: features fp32 -> fp16 ----------------
__global__ void k_convert_feat(const float* __restrict__ src) {
    size_t i = (size_t)blockIdx.x * blockDim.x + threadIdx.x;
    if (i >= NF4) return;
    float4 v = reinterpret_cast<const float4*>(src)[i];
    __half2* dst = reinterpret_cast<__half2*>(g_feat_h);
    dst[2 * i + 0] = __floats2half2_rn(v.x, v.y);
    dst[2 * i + 1] = __floats2half2_rn(v.z, v.w);
}

// ---------------- kernel 1b: W_ft fp32 -> fp16 hi/lo split ----------------
__global__ void k_convert_w(const float* __restrict__ src) {
    size_t i = (size_t)blockIdx.x * blockDim.x + threadIdx.x;
    if (i >= NW4) return;
    float4 v = reinterpret_cast<const float4*>(src)[i];
    float x[4] = {v.x, v.y, v.z, v.w};
    __half h[4], l[4];
#pragma unroll
    for (int j = 0; j < 4; ++j) {
        h[j] = __float2half_rn(x[j]);
        l[j] = __float2half_rn(x[j] - __half2float(h[j]));
    }
    reinterpret_cast<__half2*>(g_w_hi)[2 * i + 0] = __halves2half2(h[0], h[1]);
    reinterpret_cast<__half2*>(g_w_hi)[2 * i + 1] = __halves2half2(h[2], h[3]);
    reinterpret_cast<__half2*>(g_w_lo)[2 * i + 0] = __halves2half2(l[0], l[1]);
    reinterpret_cast<__half2*>(g_w_lo)[2 * i + 1] = __halves2half2(l[2], l[3]);
}

// ---------------- kernel 2: mma.sync fp16 split-2 GEMM ----------------
// C[8192,512] = feat_h[8192,41024] @ (Whi + Wlo)[512,41024]^T, fp32 accum
__global__ __launch_bounds__(256, 1) void k_gemm() {
    extern __shared__ char smem_raw[];
    const uint32_t sraw = smem_u32(smem_raw);
    const uint32_t bufs = (sraw + 1023u) & ~1023u;

    const int tid = threadIdx.x;
    const int lane = tid & 31, wid = tid >> 5;
    const int warp_m = wid >> 1, warp_n = wid & 1;
    const int rb = blockIdx.x;   // 0..31  (M tiles)
    const int nb = blockIdx.y;   // 0..3   (N tiles)

    const __half* Ag  = g_feat_h + (size_t)(rb * TILE_M) * FEAT;
    const __half* Bhg = g_w_hi + (size_t)(nb * TILE_N) * FEAT;
    const __half* Blg = g_w_lo + (size_t)(nb * TILE_N) * FEAT;

    // per-thread cp.async chunk coords (16B chunks, 128B rows, XOR swizzle)
    // swizzled within-row offset: (c16*16) ^ ((row&7)<<4)
    auto load_stage = [&](int s, int buf) {
        const uint32_t bb = bufs + (unsigned)buf * BUF_STRIDE;
        const int k0 = s * KC;
#pragma unroll
        for (int it = 0; it < 8; ++it) {            // A: 2048 chunks
            int c = tid + it * 256;
            int row = c >> 3, c16 = c & 7;
            uint32_t d = bb + OFF_A + (unsigned)(row * 128 + ((c16 * 16) ^ ((row & 7) << 4)));
            cp_async16(d, Ag + (size_t)row * FEAT + k0 + c16 * 8);
        }
#pragma unroll
        for (int it = 0; it < 4; ++it) {            // Bhi: 1024 chunks
            int c = tid + it * 256;
            int row = c >> 3, c16 = c & 7;
            uint32_t sw = (unsigned)(row * 128 + ((c16 * 16) ^ ((row & 7) << 4)));
            size_t g = (size_t)row * FEAT + k0 + c16 * 8;
            cp_async16(bb + OFF_BH + sw, Bhg + g);
            cp_async16(bb + OFF_BL + sw, Blg + g);
        }
        cp_commit();
    };

    // ldmatrix per-lane geometry
    const int rowA = lane & 15;                 // A: 16 rows, khalf = lane>>4
    const int khA  = lane >> 4;
    const int rowB = (lane & 7) + 8 * (lane >> 4);   // B: n row
    const int khB  = (lane >> 3) & 1;
    const uint32_t swz = (uint32_t)((lane & 7) << 4);

    float acc[4][8][4];
#pragma unroll
    for (int i = 0; i < 4; ++i)
#pragma unroll
        for (int j = 0; j < 8; ++j)
#pragma unroll
            for (int q = 0; q < 4; ++q) acc[i][j][q] = 0.f;

    load_stage(0, 0);
    load_stage(1, 1);

#pragma unroll 1
    for (int s = 0; s < NSTAGE; ++s) {
        if (s < NSTAGE - 1) cp_wait<1>(); else cp_wait<0>();
        __syncthreads();

        const uint32_t bb = bufs + (unsigned)(s & 1) * BUF_STRIDE;
        const uint32_t baseA  = bb + OFF_A  + (unsigned)((warp_m * 64 + rowA) * 128);
        const uint32_t baseBh = bb + OFF_BH + (unsigned)((warp_n * 64 + rowB) * 128);
        const uint32_t baseBl = bb + OFF_BL + (unsigned)((warp_n * 64 + rowB) * 128);

#pragma unroll 1
        for (int ks = 0; ks < 4; ++ks) {
            const uint32_t CA = (uint32_t)((ks * 32) | (khA * 16)) ^ swz;
            const uint32_t CB = (uint32_t)((ks * 32) | (khB * 16)) ^ swz;
            uint32_t a[4][4], bh[4][4], bl[4][4];
#pragma unroll
            for (int i = 0; i < 4; ++i)
                ldsm_x4(a[i][0], a[i][1], a[i][2], a[i][3],
                        baseA + (unsigned)(i * 16 * 128) + CA);
#pragma unroll
            for (int j2 = 0; j2 < 4; ++j2) {
                const uint32_t ro = (unsigned)(j2 * 16 * 128);
                ldsm_x4(bh[j2][0], bh[j2][1], bh[j2][2], bh[j2][3], baseBh + ro + CB);
                ldsm_x4(bl[j2][0], bl[j2][1], bl[j2][2], bl[j2][3], baseBl + ro + CB);
            }
#pragma unroll
            for (int i = 0; i < 4; ++i)
#pragma unroll
                for (int j2 = 0; j2 < 4; ++j2) {
                    mma16816(acc[i][2 * j2 + 0], a[i], &bh[j2][0]);
                    mma16816(acc[i][2 * j2 + 0], a[i], &bl[j2][0]);
                    mma16816(acc[i][2 * j2 + 1], a[i], &bh[j2][2]);
                    mma16816(acc[i][2 * j2 + 1], a[i], &bl[j2][2]);
                }
        }

        if (s + 2 < NSTAGE) {
            __syncthreads();               // all warps done reading buf before overwrite
            load_stage(s + 2, s & 1);
        }
    }

    // epilogue: fragment -> g_acc (fp32)
    const int r  = lane >> 2;
    const int cc = 2 * (lane & 3);
    const int m0 = rb * TILE_M + warp_m * 64;
    const int n0 = nb * TILE_N + warp_n * 64;
#pragma unroll
    for (int i = 0; i < 4; ++i)
#pragma unroll
        for (int j = 0; j < 8; ++j) {
            const int m = m0 + i * 16 + r;
            const int n = n0 + j * 8 + cc;
            *reinterpret_cast<float2*>(&g_acc[(size_t)m * MOUT + n]) =
                make_float2(acc[i][j][0], acc[i][j][1]);
            *reinterpret_cast<float2*>(&g_acc[(size_t)(m + 8) * MOUT + n]) =
                make_float2(acc[i][j][2], acc[i][j][3]);
        }
}

// ---------------- kernel 3: bias + stm + clip + MLP head ----------------
__global__ __launch_bounds__(128) void k_mlp(const float* __restrict__ stm,
                                             const float* __restrict__ b_ft,
                                             const float* __restrict__ W1,
                                             const float* __restrict__ b1,
                                             const float* __restrict__ W2,
                                             const float* __restrict__ b2,
                                             float* __restrict__ out) {
    __shared__ float l1[1024];
    __shared__ float l2[32];
    const int b = blockIdx.x, t = threadIdx.x;
    const float s0 = stm[b * 2 + 0], s1 = stm[b * 2 + 1];
#pragma unroll
    for (int it = 0; it < 8; ++it) {
        int i = t + it * 128;
        int p = i >> 9, m = i & 511;
        float v = (g_acc[(size_t)(b * 2 + p) * MOUT + m] + b_ft[m]) * (p ? s1 : s0);
        l1[i] = fminf(fmaxf(v, 0.f), 1.f);
    }
    __syncthreads();
    const int w = t >> 5, lane = t & 31;
#pragma unroll 1
    for (int jj = 0; jj < 8; ++jj) {
        int j = w * 8 + jj;
        const float* wr = W1 + (size_t)j * 1024;
        float s = 0.f;
#pragma unroll 8
        for (int i = lane; i < 1024; i += 32) s += l1[i] * wr[i];
#pragma unroll
        for (int o = 16; o; o >>= 1) s += __shfl_xor_sync(0xffffffffu, s, o);
        if (lane == 0) l2[j] = fminf(fmaxf(s + b1[j], 0.f), 1.f);
    }
    __syncthreads();
    if (t < 32) {
        float s = l2[t] * W2[t];
#pragma unroll
        for (int o = 16; o; o >>= 1) s += __shfl_xor_sync(0xffffffffu, s, o);
        if (t == 0) out[b] = s + b2[0];
    }
}

extern "C" void kernel_launch(void* const* d_in, const int* in_sizes, int n_in,
                              void* d_out, int out_size) {
    const float* features = (const float*)d_in[0];
    const float* stm      = (const float*)d_in[1];
    const float* W_ft     = (const float*)d_in[2];
    const float* b_ft     = (const float*)d_in[3];
    const float* W1       = (const float*)d_in[4];
    const float* b1       = (const float*)d_in[5];
    const float* W2       = (const float*)d_in[6];
    const float* b2       = (const float*)d_in[7];
    float* out = (float*)d_out;

    cudaFuncSetAttribute(k_gemm, cudaFuncAttributeMaxDynamicSharedMemorySize, DYN_SMEM);

    k_convert_feat<<<(unsigned)((NF4 + 255) / 256), 256>>>(features);
    k_convert_w<<<(unsigned)((NW4 + 255) / 256), 256>>>(W_ft);
    k_gemm<<<dim3(32, 4), 256, DYN_SMEM>>>();
    k_mlp<<<BATCH, 128>>>(stm, b_ft, W1, b1, W2, b2, out);
}

// round 12
// speedup vs baseline: 1.5507x; 1.5507x over previous
#include <cuda_runtime.h>
#include <cuda_fp16.h>
#include <cstdint>
#include <cstddef>

#define DINLINE __device__ __forceinline__

static constexpr int BATCH = 4096;
static constexpr int ROWS  = BATCH * 2;   // 8192 GEMM rows (b*2+p)
static constexpr int FEAT  = 41024;       // K
static constexpr int MOUT  = 512;         // N

// CTA tile 256x128, 256 threads, warp grid 4(M) x 2(N), warp tile 64x64
static constexpr int TILE_M = 256;
static constexpr int TILE_N = 128;
static constexpr int KC     = 64;               // fp16 K per stage (128B rows)
static constexpr int NSTAGE = FEAT / KC;        // 641 exact

static constexpr unsigned OFF_A = 0u;           // A tile 256x64 fp16 = 32KB
static constexpr unsigned OFF_B = 32768u;       // B tile 128x64 fp16 = 16KB
static constexpr unsigned BUF_STRIDE = 49152u;  // 48KB per stage
static constexpr int NBUF = 3;
static constexpr unsigned DYN_SMEM = 1024u + (unsigned)NBUF * BUF_STRIDE; // 148480

static constexpr size_t NFEL = (size_t)ROWS * FEAT;
static constexpr size_t NWEL = (size_t)MOUT * FEAT;
static constexpr size_t NF4  = NFEL / 4;
static constexpr size_t NW4  = NWEL / 4;

__device__ __align__(256) __half g_feat_h[NFEL];              // 672 MB
__device__ __align__(256) __half g_w_h[NWEL];                 // 42 MB
__device__ __align__(256) float  g_acc[(size_t)ROWS * MOUT];  // 16 MB
__device__ __align__(256) float  g_corr[MOUT];                // w_lo mean correction

// ---------------- PTX helpers (base ISA, sm_80+) ----------------
DINLINE uint32_t smem_u32(const void* p) {
    uint32_t a;
    asm("{ .reg .u64 t; cvta.to.shared.u64 t, %1; cvt.u32.u64 %0, t; }" : "=r"(a) : "l"(p));
    return a;
}
DINLINE void cp_async16(uint32_t dst, const void* src) {
    asm volatile("cp.async.cg.shared.global [%0], [%1], 16;" :: "r"(dst), "l"(src) : "memory");
}
DINLINE void cp_commit() { asm volatile("cp.async.commit_group;" ::: "memory"); }
template <int N> DINLINE void cp_wait() { asm volatile("cp.async.wait_group %0;" :: "n"(N) : "memory"); }

DINLINE void ldsm_x4(uint32_t& r0, uint32_t& r1, uint32_t& r2, uint32_t& r3, uint32_t a) {
    asm volatile("ldmatrix.sync.aligned.m8n8.x4.shared.b16 {%0,%1,%2,%3}, [%4];"
                 : "=r"(r0), "=r"(r1), "=r"(r2), "=r"(r3) : "r"(a));
}
DINLINE void mma16816(float* c, const uint32_t* a, const uint32_t* b) {
    asm volatile(
        "mma.sync.aligned.m16n8k16.row.col.f32.f16.f16.f32 "
        "{%0,%1,%2,%3}, {%4,%5,%6,%7}, {%8,%9}, {%0,%1,%2,%3};"
        : "+f"(c[0]), "+f"(c[1]), "+f"(c[2]), "+f"(c[3])
        : "r"(a[0]), "r"(a[1]), "r"(a[2]), "r"(a[3]), "r"(b[0]), "r"(b[1]));
}

// ---------------- kernel 1a: features fp32 -> fp16 ----------------
__global__ void k_convert_feat(const float* __restrict__ src) {
    size_t i = (size_t)blockIdx.x * blockDim.x + threadIdx.x;
    if (i >= NF4) return;
    float4 v = reinterpret_cast<const float4*>(src)[i];
    __half2* dst = reinterpret_cast<__half2*>(g_feat_h);
    dst[2 * i + 0] = __floats2half2_rn(v.x, v.y);
    dst[2 * i + 1] = __floats2half2_rn(v.z, v.w);
}

// ---------------- kernel 1b: W_ft fp32 -> fp16 ----------------
__global__ void k_convert_w(const float* __restrict__ src) {
    size_t i = (size_t)blockIdx.x * blockDim.x + threadIdx.x;
    if (i >= NW4) return;
    float4 v = reinterpret_cast<const float4*>(src)[i];
    __half2* dst = reinterpret_cast<__half2*>(g_w_h);
    dst[2 * i + 0] = __floats2half2_rn(v.x, v.y);
    dst[2 * i + 1] = __floats2half2_rn(v.z, v.w);
}

// ---------------- kernel 1c: per-neuron mean correction for dropped w_lo ----------------
// corr[m] = E[f] * sum_k (w - fp16(w)) = 0.5 * sum_k w_lo[m,k]
__global__ __launch_bounds__(256) void k_wcorr(const float* __restrict__ W) {
    __shared__ float red[8];
    const int m = blockIdx.x, t = threadIdx.x;
    const float* row = W + (size_t)m * FEAT;
    float s = 0.f;
    for (int k = t; k < FEAT; k += 256) {
        float w = row[k];
        s += w - __half2float(__float2half_rn(w));
    }
#pragma unroll
    for (int o = 16; o; o >>= 1) s += __shfl_xor_sync(0xffffffffu, s, o);
    if ((t & 31) == 0) red[t >> 5] = s;
    __syncthreads();
    if (t < 8) {
        s = red[t];
#pragma unroll
        for (int o = 4; o; o >>= 1) s += __shfl_xor_sync(0xffu, s, o);
        if (t == 0) g_corr[m] = 0.5f * s;
    }
}

// ---------------- kernel 2: mma.sync fp16 GEMM ----------------
// g_acc[8192,512] = feat_h[8192,41024] @ w_h[512,41024]^T, fp32 accum
__global__ __launch_bounds__(256, 1) void k_gemm() {
    extern __shared__ char smem_raw[];
    const uint32_t sraw = smem_u32(smem_raw);
    const uint32_t bufs = (sraw + 1023u) & ~1023u;

    const int tid = threadIdx.x;
    const int lane = tid & 31, wid = tid >> 5;
    const int warp_m = wid >> 1, warp_n = wid & 1;
    const int rb = blockIdx.x;   // 0..31 (M tiles)
    const int nb = blockIdx.y;   // 0..3  (N tiles)

    const __half* Ag = g_feat_h + (size_t)(rb * TILE_M) * FEAT;
    const __half* Bg = g_w_h + (size_t)(nb * TILE_N) * FEAT;

    // 16B-chunk loader, 128B smem rows, XOR swizzle ((row&7)<<4)
    auto load_stage = [&](int s, int buf) {
        const uint32_t bb = bufs + (unsigned)buf * BUF_STRIDE;
        const int k0 = s * KC;
#pragma unroll
        for (int it = 0; it < 8; ++it) {            // A: 2048 chunks
            int c = tid + it * 256;
            int row = c >> 3, c16 = c & 7;
            uint32_t d = bb + OFF_A + (unsigned)(row * 128 + ((c16 * 16) ^ ((row & 7) << 4)));
            cp_async16(d, Ag + (size_t)row * FEAT + k0 + c16 * 8);
        }
#pragma unroll
        for (int it = 0; it < 4; ++it) {            // B: 1024 chunks
            int c = tid + it * 256;
            int row = c >> 3, c16 = c & 7;
            uint32_t d = bb + OFF_B + (unsigned)(row * 128 + ((c16 * 16) ^ ((row & 7) << 4)));
            cp_async16(d, Bg + (size_t)row * FEAT + k0 + c16 * 8);
        }
        cp_commit();
    };

    // ldmatrix per-lane geometry (validated in R11)
    const int rowA = lane & 15;
    const int khA  = lane >> 4;
    const int rowB = (lane & 7) + 8 * (lane >> 4);
    const int khB  = (lane >> 3) & 1;
    const uint32_t swz = (uint32_t)((lane & 7) << 4);

    float acc[4][8][4];
#pragma unroll
    for (int i = 0; i < 4; ++i)
#pragma unroll
        for (int j = 0; j < 8; ++j)
#pragma unroll
            for (int q = 0; q < 4; ++q) acc[i][j][q] = 0.f;

    load_stage(0, 0);
    load_stage(1, 1);

#pragma unroll 1
    for (int s = 0; s < NSTAGE; ++s) {
        if (s < NSTAGE - 1) cp_wait<1>(); else cp_wait<0>();
        __syncthreads();  // stage s visible; also all warps done computing s-1

        if (s + 2 < NSTAGE) load_stage(s + 2, (s + 2) % NBUF);  // buf (s-1)%3: free

        const uint32_t bb = bufs + (unsigned)(s % NBUF) * BUF_STRIDE;
        const uint32_t baseA = bb + OFF_A + (unsigned)((warp_m * 64 + rowA) * 128);
        const uint32_t baseB = bb + OFF_B + (unsigned)((warp_n * 64 + rowB) * 128);

#pragma unroll
        for (int ks = 0; ks < 4; ++ks) {
            const uint32_t CA = (uint32_t)((ks * 32) | (khA * 16)) ^ swz;
            const uint32_t CB = (uint32_t)((ks * 32) | (khB * 16)) ^ swz;
            uint32_t a[4][4], b[4][4];
#pragma unroll
            for (int i = 0; i < 4; ++i)
                ldsm_x4(a[i][0], a[i][1], a[i][2], a[i][3],
                        baseA + (unsigned)(i * 16 * 128) + CA);
#pragma unroll
            for (int j2 = 0; j2 < 4; ++j2)
                ldsm_x4(b[j2][0], b[j2][1], b[j2][2], b[j2][3],
                        baseB + (unsigned)(j2 * 16 * 128) + CB);
#pragma unroll
            for (int i = 0; i < 4; ++i)
#pragma unroll
                for (int j2 = 0; j2 < 4; ++j2) {
                    mma16816(acc[i][2 * j2 + 0], a[i], &b[j2][0]);
                    mma16816(acc[i][2 * j2 + 1], a[i], &b[j2][2]);
                }
        }
    }

    // epilogue: fragments -> g_acc (fp32)
    const int r  = lane >> 2;
    const int cc = 2 * (lane & 3);
    const int m0 = rb * TILE_M + warp_m * 64;
    const int n0 = nb * TILE_N + warp_n * 64;
#pragma unroll
    for (int i = 0; i < 4; ++i)
#pragma unroll
        for (int j = 0; j < 8; ++j) {
            const int m = m0 + i * 16 + r;
            const int n = n0 + j * 8 + cc;
            *reinterpret_cast<float2*>(&g_acc[(size_t)m * MOUT + n]) =
                make_float2(acc[i][j][0], acc[i][j][1]);
            *reinterpret_cast<float2*>(&g_acc[(size_t)(m + 8) * MOUT + n]) =
                make_float2(acc[i][j][2], acc[i][j][3]);
        }
}

// ---------------- kernel 3: bias + corr + stm + clip + MLP head ----------------
__global__ __launch_bounds__(128) void k_mlp(const float* __restrict__ stm,
                                             const float* __restrict__ b_ft,
                                             const float* __restrict__ W1,
                                             const float* __restrict__ b1,
                                             const float* __restrict__ W2,
                                             const float* __restrict__ b2,
                                             float* __restrict__ out) {
    __shared__ float l1[1024];
    __shared__ float l2[32];
    const int b = blockIdx.x, t = threadIdx.x;
    const float s0 = stm[b * 2 + 0], s1 = stm[b * 2 + 1];
#pragma unroll
    for (int it = 0; it < 8; ++it) {
        int i = t + it * 128;
        int p = i >> 9, m = i & 511;
        float v = (g_acc[(size_t)(b * 2 + p) * MOUT + m] + g_corr[m] + b_ft[m]) * (p ? s1 : s0);
        l1[i] = fminf(fmaxf(v, 0.f), 1.f);
    }
    __syncthreads();
    const int w = t >> 5, lane = t & 31;
#pragma unroll 1
    for (int jj = 0; jj < 8; ++jj) {
        int j = w * 8 + jj;
        const float* wr = W1 + (size_t)j * 1024;
        float s = 0.f;
#pragma unroll 8
        for (int i = lane; i < 1024; i += 32) s += l1[i] * wr[i];
#pragma unroll
        for (int o = 16; o; o >>= 1) s += __shfl_xor_sync(0xffffffffu, s, o);
        if (lane == 0) l2[j] = fminf(fmaxf(s + b1[j], 0.f), 1.f);
    }
    __syncthreads();
    if (t < 32) {
        float s = l2[t] * W2[t];
#pragma unroll
        for (int o = 16; o; o >>= 1) s += __shfl_xor_sync(0xffffffffu, s, o);
        if (t == 0) out[b] = s + b2[0];
    }
}

extern "C" void kernel_launch(void* const* d_in, const int* in_sizes, int n_in,
                              void* d_out, int out_size) {
    const float* features = (const float*)d_in[0];
    const float* stm      = (const float*)d_in[1];
    const float* W_ft     = (const float*)d_in[2];
    const float* b_ft     = (const float*)d_in[3];
    const float* W1       = (const float*)d_in[4];
    const float* b1       = (const float*)d_in[5];
    const float* W2       = (const float*)d_in[6];
    const float* b2       = (const float*)d_in[7];
    float* out = (float*)d_out;

    cudaFuncSetAttribute(k_gemm, cudaFuncAttributeMaxDynamicSharedMemorySize, DYN_SMEM);

    k_convert_feat<<<(unsigned)((NF4 + 255) / 256), 256>>>(features);
    k_convert_w<<<(unsigned)((NW4 + 255) / 256), 256>>>(W_ft);
    k_wcorr<<<MOUT, 256>>>(W_ft);
    k_gemm<<<dim3(32, 4), 256, DYN_SMEM>>>();
    k_mlp<<<BATCH, 128>>>(stm, b_ft, W1, b1, W2, b2, out);
}

// round 13
// speedup vs baseline: 1.5894x; 1.0250x over previous
#include <cuda_runtime.h>
#include <cuda_fp16.h>
#include <cstdint>
#include <cstddef>

#define DINLINE __device__ __forceinline__

static constexpr int BATCH = 4096;
static constexpr int ROWS  = BATCH * 2;   // 8192 GEMM rows
static constexpr int FEAT  = 41024;       // K
static constexpr int MOUT  = 512;         // N

// CTA tile 128x128, 256 threads, warp grid 4(M) x 2(N), warp tile 32x64
static constexpr int TILE_M = 128;
static constexpr int TILE_N = 128;
static constexpr int KC     = 64;               // fp16 K per stage (128B rows)
static constexpr int NSTAGE = FEAT / KC;        // 641 exact

static constexpr unsigned OFF_A = 0u;           // A tile 128x64 fp16 = 16KB
static constexpr unsigned OFF_B = 16384u;       // B tile 128x64 fp16 = 16KB
static constexpr unsigned BUF_STRIDE = 32768u;  // 32KB per stage
static constexpr int NBUF = 3;
static constexpr unsigned DYN_SMEM = 1024u + (unsigned)NBUF * BUF_STRIDE; // 99328

static constexpr size_t NFEL = (size_t)ROWS * FEAT;
static constexpr size_t NWEL = (size_t)MOUT * FEAT;
static constexpr size_t NF4  = NFEL / 4;
static constexpr size_t NW4  = NWEL / 4;

__device__ __align__(256) __half g_feat_h[NFEL];              // 672 MB
__device__ __align__(256) __half g_w_h[NWEL];                 // 42 MB
__device__ __align__(256) float  g_acc[(size_t)ROWS * MOUT];  // 16 MB
__device__ __align__(256) float  g_corr[MOUT];                // w_lo mean correction

// ---------------- PTX helpers (base ISA, sm_80+) ----------------
DINLINE uint32_t smem_u32(const void* p) {
    uint32_t a;
    asm("{ .reg .u64 t; cvta.to.shared.u64 t, %1; cvt.u32.u64 %0, t; }" : "=r"(a) : "l"(p));
    return a;
}
DINLINE void cp_async16(uint32_t dst, const void* src) {
    asm volatile("cp.async.cg.shared.global [%0], [%1], 16;" :: "r"(dst), "l"(src) : "memory");
}
DINLINE void cp_commit() { asm volatile("cp.async.commit_group;" ::: "memory"); }
template <int N> DINLINE void cp_wait() { asm volatile("cp.async.wait_group %0;" :: "n"(N) : "memory"); }

DINLINE void ldsm_x4(uint32_t& r0, uint32_t& r1, uint32_t& r2, uint32_t& r3, uint32_t a) {
    asm volatile("ldmatrix.sync.aligned.m8n8.x4.shared.b16 {%0,%1,%2,%3}, [%4];"
                 : "=r"(r0), "=r"(r1), "=r"(r2), "=r"(r3) : "r"(a));
}
DINLINE void mma16816(float* c, const uint32_t* a, const uint32_t* b) {
    asm volatile(
        "mma.sync.aligned.m16n8k16.row.col.f32.f16.f16.f32 "
        "{%0,%1,%2,%3}, {%4,%5,%6,%7}, {%8,%9}, {%0,%1,%2,%3};"
        : "+f"(c[0]), "+f"(c[1]), "+f"(c[2]), "+f"(c[3])
        : "r"(a[0]), "r"(a[1]), "r"(a[2]), "r"(a[3]), "r"(b[0]), "r"(b[1]));
}

// ---------------- kernel 1a: features fp32 -> fp16 ----------------
__global__ void k_convert_feat(const float* __restrict__ src) {
    size_t i = (size_t)blockIdx.x * blockDim.x + threadIdx.x;
    if (i >= NF4) return;
    float4 v = reinterpret_cast<const float4*>(src)[i];
    __half2* dst = reinterpret_cast<__half2*>(g_feat_h);
    dst[2 * i + 0] = __floats2half2_rn(v.x, v.y);
    dst[2 * i + 1] = __floats2half2_rn(v.z, v.w);
}

// ---------------- kernel 1b: W_ft fp32 -> fp16 ----------------
__global__ void k_convert_w(const float* __restrict__ src) {
    size_t i = (size_t)blockIdx.x * blockDim.x + threadIdx.x;
    if (i >= NW4) return;
    float4 v = reinterpret_cast<const float4*>(src)[i];
    __half2* dst = reinterpret_cast<__half2*>(g_w_h);
    dst[2 * i + 0] = __floats2half2_rn(v.x, v.y);
    dst[2 * i + 1] = __floats2half2_rn(v.z, v.w);
}

// ---------------- kernel 1c: per-neuron mean correction for dropped w_lo ----------------
// corr[m] = E[f] * sum_k (w - fp16(w)) = 0.5 * sum_k w_lo[m,k]
__global__ __launch_bounds__(256) void k_wcorr(const float* __restrict__ W) {
    __shared__ float red[8];
    const int m = blockIdx.x, t = threadIdx.x;
    const float* row = W + (size_t)m * FEAT;
    float s = 0.f;
    for (int k = t; k < FEAT; k += 256) {
        float w = row[k];
        s += w - __half2float(__float2half_rn(w));
    }
#pragma unroll
    for (int o = 16; o; o >>= 1) s += __shfl_xor_sync(0xffffffffu, s, o);
    if ((t & 31) == 0) red[t >> 5] = s;
    __syncthreads();
    if (t < 8) {
        s = red[t];
#pragma unroll
        for (int o = 4; o; o >>= 1) s += __shfl_xor_sync(0xffu, s, o);
        if (t == 0) g_corr[m] = 0.5f * s;
    }
}

// ---------------- kernel 2: mma.sync fp16 GEMM, 2 CTAs/SM ----------------
__global__ __launch_bounds__(256, 2) void k_gemm() {
    extern __shared__ char smem_raw[];
    const uint32_t sraw = smem_u32(smem_raw);
    const uint32_t bufs = (sraw + 1023u) & ~1023u;

    const int tid = threadIdx.x;
    const int lane = tid & 31, wid = tid >> 5;
    const int warp_m = wid >> 1, warp_n = wid & 1;   // 4 x 2
    const int rb = blockIdx.x;   // 0..63 (M tiles)
    const int nb = blockIdx.y;   // 0..3  (N tiles)

    const __half* Ag = g_feat_h + (size_t)(rb * TILE_M) * FEAT;
    const __half* Bg = g_w_h + (size_t)(nb * TILE_N) * FEAT;

    // 16B-chunk loader, 128B smem rows, XOR swizzle ((row&7)<<4)
    auto load_stage = [&](int s, int buf) {
        const uint32_t bb = bufs + (unsigned)buf * BUF_STRIDE;
        const int k0 = s * KC;
#pragma unroll
        for (int it = 0; it < 4; ++it) {            // A: 1024 chunks
            int c = tid + it * 256;
            int row = c >> 3, c16 = c & 7;
            uint32_t d = bb + OFF_A + (unsigned)(row * 128 + ((c16 * 16) ^ ((row & 7) << 4)));
            cp_async16(d, Ag + (size_t)row * FEAT + k0 + c16 * 8);
        }
#pragma unroll
        for (int it = 0; it < 4; ++it) {            // B: 1024 chunks
            int c = tid + it * 256;
            int row = c >> 3, c16 = c & 7;
            uint32_t d = bb + OFF_B + (unsigned)(row * 128 + ((c16 * 16) ^ ((row & 7) << 4)));
            cp_async16(d, Bg + (size_t)row * FEAT + k0 + c16 * 8);
        }
        cp_commit();
    };

    // ldmatrix per-lane geometry (validated R11/R12)
    const int rowA = lane & 15;
    const int khA  = lane >> 4;
    const int rowB = (lane & 7) + 8 * (lane >> 4);
    const int khB  = (lane >> 3) & 1;
    const uint32_t swz = (uint32_t)((lane & 7) << 4);

    float acc[2][8][4];
#pragma unroll
    for (int i = 0; i < 2; ++i)
#pragma unroll
        for (int j = 0; j < 8; ++j)
#pragma unroll
            for (int q = 0; q < 4; ++q) acc[i][j][q] = 0.f;

    load_stage(0, 0);
    load_stage(1, 1);

#pragma unroll 1
    for (int s = 0; s < NSTAGE; ++s) {
        if (s < NSTAGE - 1) cp_wait<1>(); else cp_wait<0>();
        __syncthreads();  // stage s visible; all warps done with stage s-1

        if (s + 2 < NSTAGE) load_stage(s + 2, (s + 2) % NBUF);  // buf (s-1)%3 is free

        const uint32_t bb = bufs + (unsigned)(s % NBUF) * BUF_STRIDE;
        const uint32_t baseA = bb + OFF_A + (unsigned)((warp_m * 32 + rowA) * 128);
        const uint32_t baseB = bb + OFF_B + (unsigned)((warp_n * 64 + rowB) * 128);

#pragma unroll
        for (int ks = 0; ks < 4; ++ks) {
            const uint32_t CA = (uint32_t)((ks * 32) | (khA * 16)) ^ swz;
            const uint32_t CB = (uint32_t)((ks * 32) | (khB * 16)) ^ swz;
            uint32_t a[2][4], b[4][4];
#pragma unroll
            for (int i = 0; i < 2; ++i)
                ldsm_x4(a[i][0], a[i][1], a[i][2], a[i][3],
                        baseA + (unsigned)(i * 16 * 128) + CA);
#pragma unroll
            for (int j2 = 0; j2 < 4; ++j2)
                ldsm_x4(b[j2][0], b[j2][1], b[j2][2], b[j2][3],
                        baseB + (unsigned)(j2 * 16 * 128) + CB);
#pragma unroll
            for (int i = 0; i < 2; ++i)
#pragma unroll
                for (int j2 = 0; j2 < 4; ++j2) {
                    mma16816(acc[i][2 * j2 + 0], a[i], &b[j2][0]);
                    mma16816(acc[i][2 * j2 + 1], a[i], &b[j2][2]);
                }
        }
    }

    // epilogue: fragments -> g_acc (fp32)
    const int r  = lane >> 2;
    const int cc = 2 * (lane & 3);
    const int m0 = rb * TILE_M + warp_m * 32;
    const int n0 = nb * TILE_N + warp_n * 64;
#pragma unroll
    for (int i = 0; i < 2; ++i)
#pragma unroll
        for (int j = 0; j < 8; ++j) {
            const int m = m0 + i * 16 + r;
            const int n = n0 + j * 8 + cc;
            *reinterpret_cast<float2*>(&g_acc[(size_t)m * MOUT + n]) =
                make_float2(acc[i][j][0], acc[i][j][1]);
            *reinterpret_cast<float2*>(&g_acc[(size_t)(m + 8) * MOUT + n]) =
                make_float2(acc[i][j][2], acc[i][j][3]);
        }
}

// ---------------- kernel 3: bias + corr + stm + clip + MLP head ----------------
__global__ __launch_bounds__(128) void k_mlp(const float* __restrict__ stm,
                                             const float* __restrict__ b_ft,
                                             const float* __restrict__ W1,
                                             const float* __restrict__ b1,
                                             const float* __restrict__ W2,
                                             const float* __restrict__ b2,
                                             float* __restrict__ out) {
    __shared__ float l1[1024];
    __shared__ float l2[32];
    const int b = blockIdx.x, t = threadIdx.x;
    const float s0 = stm[b * 2 + 0], s1 = stm[b * 2 + 1];
#pragma unroll
    for (int it = 0; it < 8; ++it) {
        int i = t + it * 128;
        int p = i >> 9, m = i & 511;
        float v = (g_acc[(size_t)(b * 2 + p) * MOUT + m] + g_corr[m] + b_ft[m]) * (p ? s1 : s0);
        l1[i] = fminf(fmaxf(v, 0.f), 1.f);
    }
    __syncthreads();
    const int w = t >> 5, lane = t & 31;
#pragma unroll 1
    for (int jj = 0; jj < 8; ++jj) {
        int j = w * 8 + jj;
        const float* wr = W1 + (size_t)j * 1024;
        float s = 0.f;
#pragma unroll 8
        for (int i = lane; i < 1024; i += 32) s += l1[i] * wr[i];
#pragma unroll
        for (int o = 16; o; o >>= 1) s += __shfl_xor_sync(0xffffffffu, s, o);
        if (lane == 0) l2[j] = fminf(fmaxf(s + b1[j], 0.f), 1.f);
    }
    __syncthreads();
    if (t < 32) {
        float s = l2[t] * W2[t];
#pragma unroll
        for (int o = 16; o; o >>= 1) s += __shfl_xor_sync(0xffffffffu, s, o);
        if (t == 0) out[b] = s + b2[0];
    }
}

extern "C" void kernel_launch(void* const* d_in, const int* in_sizes, int n_in,
                              void* d_out, int out_size) {
    const float* features = (const float*)d_in[0];
    const float* stm      = (const float*)d_in[1];
    const float* W_ft     = (const float*)d_in[2];
    const float* b_ft     = (const float*)d_in[3];
    const float* W1       = (const float*)d_in[4];
    const float* b1       = (const float*)d_in[5];
    const float* W2       = (const float*)d_in[6];
    const float* b2       = (const float*)d_in[7];
    float* out = (float*)d_out;

    cudaFuncSetAttribute(k_gemm, cudaFuncAttributeMaxDynamicSharedMemorySize, DYN_SMEM);

    k_convert_feat<<<(unsigned)((NF4 + 255) / 256), 256>>>(features);
    k_convert_w<<<(unsigned)((NW4 + 255) / 256), 256>>>(W_ft);
    k_wcorr<<<MOUT, 256>>>(W_ft);
    k_gemm<<<dim3(64, 4), 256, DYN_SMEM>>>();
    k_mlp<<<BATCH, 128>>>(stm, b_ft, W1, b1, W2, b2, out);
}